// round 13
// baseline (speedup 1.0000x reference)
#include <cuda_runtime.h>
#include <cuda_bf16.h>

// Problem constants
#define B_ 8
#define S_ 512
#define E_ 1024
#define H_ 16
#define D_ 64
#define M_ (B_*S_)     // 4096 rows for projection GEMMs
#define QT_ (S_/64)    // 8 q-tiles per (b,h)

// Scratch: __device__ globals (no allocation allowed anywhere)
__device__ float g_q[B_*H_*S_*D_];    // 16 MB, [B,H,S,D]
__device__ float g_k[B_*H_*S_*D_];
__device__ float g_v[B_*H_*S_*D_];
__device__ float g_ctx[B_*S_*E_];     // 16 MB, [B,S,E]

// ----------------------------------------------------------------------------
// tf32 helpers (PTX-ISA m16n8k8 fragment conventions, sm_80 lineage):
//   A row-major:  a0=(g,ct) a1=(g+8,ct) a2=(g,ct+4) a3=(g+8,ct+4)
//   B col-major:  b0=(k=ct,n=g) b1=(k=ct+4,n=g)
//   C:            c0/c1=(g,2ct/2ct+1) c2/c3=(g+8,.)
// with g=lane>>2, ct=lane&3.
// tf32x3 split: x = hi + lo, hi = rna_tf32(x), lo = rna_tf32(x - hi);
// A.B ~= Ah.Bh + Ah.Bl + Al.Bh  (error ~2^-22, fp32-class).
// ----------------------------------------------------------------------------
__device__ __forceinline__ unsigned f2tf32(float x) {
    unsigned r;
    asm("cvt.rna.tf32.f32 %0, %1;" : "=r"(r) : "f"(x));
    return r;
}
__device__ __forceinline__ void split_tf32(float x, unsigned& hi, unsigned& lo) {
    hi = f2tf32(x);
    lo = f2tf32(x - __uint_as_float(hi));
}

__device__ __forceinline__ void mma_tf32(float* d, const unsigned* a,
                                         const unsigned* b) {
    asm("mma.sync.aligned.m16n8k8.row.col.f32.tf32.tf32.f32 "
        "{%0,%1,%2,%3}, {%4,%5,%6,%7}, {%8,%9}, {%0,%1,%2,%3};\n"
        : "+f"(d[0]), "+f"(d[1]), "+f"(d[2]), "+f"(d[3])
        : "r"(a[0]), "r"(a[1]), "r"(a[2]), "r"(a[3]),
          "r"(b[0]), "r"(b[1]));
}

// ----------------------------------------------------------------------------
// tf32x3 tensor-core GEMM: C[m,n] = sum_k A[m,k]*W[n,k] + bias[n]  (fp32-class
// accuracy). Both operands K-contiguous row-major: mma "row.col" consumes
// W[n,k] directly as col-major B. CTA tile 128x128, K-tile 16,
// DOUBLE-buffered hi/lo smem (80KB dynamic) + register prefetch: ONE
// __syncthreads per k-tile; split+STS of tile t+1 overlaps mma tail of t.
// 8 warps (2x4); warp tile 64x32 = 4x4 m16n8k8 tiles per k-step of 8;
// 3 mma per tile (hh, hl, lh). Smem row stride 20 words: fragment LDS
// addresses (g*20+ct) map to 32 distinct banks -> conflict-free.
// Bias loaded BEFORE the mainloop (L1-resident by the epilogue; removes the
// exposed L2/DRAM tail after the last barrier).
// head_layout=1 remaps store (m,n) -> [B,H,S,D].
// ----------------------------------------------------------------------------
#define GST_ 20
#define KT_ 16
#define GPLANE_ (128 * GST_)              // 2560 words per plane
#define GSMEM_BYTES_ (8 * GPLANE_ * 4)    // 2 bufs x 4 planes = 81920 B

extern __shared__ unsigned gsm[];

__device__ __forceinline__ void gemm_tf32_body(
    const float* __restrict__ A, const float* __restrict__ W,
    const float* __restrict__ bias, float* __restrict__ C,
    int row0, int col0, int head_layout)
{
    // Plane layout: [{AsH,AsL,WsH,WsL}][buf][2560]
    unsigned* AsH = gsm;
    unsigned* AsL = gsm + 2 * GPLANE_;
    unsigned* WsH = gsm + 4 * GPLANE_;
    unsigned* WsL = gsm + 6 * GPLANE_;

    int t    = threadIdx.x;
    int w    = t >> 5, lane = t & 31;
    int g    = lane >> 2, ct = lane & 3;
    int wm   = w & 1,  wn = w >> 1;
    int mbase = wm * 64, nbase = wn * 32;

    int lr = t >> 1;          // staging row 0..127
    int lk = (t & 1) * 8;     // staging k-segment 0 or 8

    const float* Ap = A + (size_t)(row0 + lr) * E_ + lk;
    const float* Wp = W + (size_t)(col0 + lr) * E_ + lk;

    // Bias prefetch: issued now, consumed in the epilogue (hot in L1 by then)
    float2 bias_pre[4];
    #pragma unroll
    for (int nt = 0; nt < 4; nt++)
        bias_pre[nt] = *(const float2*)&bias[col0 + nbase + nt * 8 + ct * 2];

    float acc[4][4][4];
    #pragma unroll
    for (int i = 0; i < 4; i++)
        #pragma unroll
        for (int j = 0; j < 4; j++)
            #pragma unroll
            for (int r = 0; r < 4; r++) acc[i][j][r] = 0.f;

    // Stage k-tile 0 into buffer 0 (split to hi/lo in-flight)
    {
        float av[8], wv[8];
        *(float4*)&av[0] = *(const float4*)(Ap);
        *(float4*)&av[4] = *(const float4*)(Ap + 4);
        *(float4*)&wv[0] = *(const float4*)(Wp);
        *(float4*)&wv[4] = *(const float4*)(Wp + 4);
        #pragma unroll
        for (int i = 0; i < 8; i++) {
            unsigned h, l;
            split_tf32(av[i], h, l);
            AsH[lr * GST_ + lk + i] = h; AsL[lr * GST_ + lk + i] = l;
            split_tf32(wv[i], h, l);
            WsH[lr * GST_ + lk + i] = h; WsL[lr * GST_ + lk + i] = l;
        }
    }
    __syncthreads();

    int buf = 0;
    for (int k0 = KT_; k0 <= E_; k0 += KT_) {
        // Prefetch next k-tile into registers (overlaps with mma below)
        float av[8], wv[8];
        if (k0 < E_) {
            *(float4*)&av[0] = *(const float4*)(Ap + k0);
            *(float4*)&av[4] = *(const float4*)(Ap + k0 + 4);
            *(float4*)&wv[0] = *(const float4*)(Wp + k0);
            *(float4*)&wv[4] = *(const float4*)(Wp + k0 + 4);
        }

        int bo = buf * GPLANE_;
        // Compute on current buffer: 2 k-steps x (4x4 tiles) x 3 mma
        #pragma unroll
        for (int ks = 0; ks < KT_; ks += 8) {
            unsigned bfh[4][2], bfl[4][2];
            #pragma unroll
            for (int nt = 0; nt < 4; nt++) {
                int base = bo + (nbase + nt * 8 + g) * GST_ + ks + ct;
                bfh[nt][0] = WsH[base]; bfh[nt][1] = WsH[base + 4];
                bfl[nt][0] = WsL[base]; bfl[nt][1] = WsL[base + 4];
            }
            #pragma unroll
            for (int mt = 0; mt < 4; mt++) {
                int base = bo + (mbase + mt * 16 + g) * GST_ + ks + ct;
                unsigned afh[4] = {AsH[base], AsH[base + 8 * GST_],
                                   AsH[base + 4], AsH[base + 8 * GST_ + 4]};
                unsigned afl[4] = {AsL[base], AsL[base + 8 * GST_],
                                   AsL[base + 4], AsL[base + 8 * GST_ + 4]};
                #pragma unroll
                for (int nt = 0; nt < 4; nt++) {
                    mma_tf32(acc[mt][nt], afh, bfh[nt]);
                    mma_tf32(acc[mt][nt], afh, bfl[nt]);
                    mma_tf32(acc[mt][nt], afl, bfh[nt]);
                }
            }
        }

        if (k0 < E_) {
            int nbuf = buf ^ 1;
            int no = nbuf * GPLANE_;
            // Split + STS into the other buffer (no barrier needed before:
            // everyone is reading buf, nobody touches nbuf)
            #pragma unroll
            for (int i = 0; i < 8; i++) {
                unsigned h, l;
                split_tf32(av[i], h, l);
                AsH[no + lr * GST_ + lk + i] = h;
                AsL[no + lr * GST_ + lk + i] = l;
                split_tf32(wv[i], h, l);
                WsH[no + lr * GST_ + lk + i] = h;
                WsL[no + lr * GST_ + lk + i] = l;
            }
            __syncthreads();   // stores visible before next compute
            buf = nbuf;
        }
    }

    // Epilogue: bias (prefetched) + store. c0/c1 -> (row, 2ct/2ct+1), c2/c3 -> row+8.
    #pragma unroll
    for (int mt = 0; mt < 4; mt++) {
        int r = row0 + mbase + mt * 16 + g;
        #pragma unroll
        for (int nt = 0; nt < 4; nt++) {
            int c = col0 + nbase + nt * 8 + ct * 2;
            float2 bv = bias_pre[nt];
            float2 lo = make_float2(acc[mt][nt][0] + bv.x,
                                    acc[mt][nt][1] + bv.y);
            float2 hi = make_float2(acc[mt][nt][2] + bv.x,
                                    acc[mt][nt][3] + bv.y);
            if (head_layout) {
                int hh = c >> 6, dd = c & 63;
                int bb0 = r >> 9, ss0 = r & 511;
                int r2 = r + 8;
                int bb1 = r2 >> 9, ss1 = r2 & 511;
                *(float2*)&C[(((size_t)(bb0*H_ + hh))*S_ + ss0)*D_ + dd] = lo;
                *(float2*)&C[(((size_t)(bb1*H_ + hh))*S_ + ss1)*D_ + dd] = hi;
            } else {
                *(float2*)&C[(size_t)r * E_ + c]       = lo;
                *(float2*)&C[(size_t)(r + 8) * E_ + c] = hi;
            }
        }
    }
}

// Fused Q/K/V projections: gridDim.z = 3 selects (x, W, bias, dst).
__global__ __launch_bounds__(256, 2) void qkv_proj_kernel(
    const float* __restrict__ xq, const float* __restrict__ xk,
    const float* __restrict__ xv,
    const float* __restrict__ Wq, const float* __restrict__ Wk,
    const float* __restrict__ Wv,
    const float* __restrict__ bq, const float* __restrict__ bk,
    const float* __restrict__ bv,
    float* __restrict__ q, float* __restrict__ k, float* __restrict__ v)
{
    int z = blockIdx.z;
    const float* A    = (z == 0) ? xq : (z == 1) ? xk : xv;
    const float* W    = (z == 0) ? Wq : (z == 1) ? Wk : Wv;
    const float* bias = (z == 0) ? bq : (z == 1) ? bk : bv;
    float*       C    = (z == 0) ? q  : (z == 1) ? k  : v;
    gemm_tf32_body(A, W, bias, C, blockIdx.y * 128, blockIdx.x * 128, 1);
}

// Output projection (flat [B*S, E] store)
__global__ __launch_bounds__(256, 2) void out_proj_kernel(
    const float* __restrict__ A, const float* __restrict__ W,
    const float* __restrict__ bias, float* __restrict__ C)
{
    gemm_tf32_body(A, W, bias, C, blockIdx.y * 128, blockIdx.x * 128, 0);
}

// ----------------------------------------------------------------------------
// Fused RoPE (interleaved pairs) + L2 normalization, in-place on [B,H,S,D].
// One warp per (b,h,s) row; lane owns pair (2*lane, 2*lane+1).
// Processes BOTH q and k in one launch (second half of grid -> k).
// ----------------------------------------------------------------------------
__global__ __launch_bounds__(256) void rope_l2norm_kernel(
    float* __restrict__ Xq, float* __restrict__ Xk,
    const float* __restrict__ cosT, const float* __restrict__ sinT)
{
    int gw   = (blockIdx.x * blockDim.x + threadIdx.x) >> 5;
    int lane = threadIdx.x & 31;
    const int NW = B_*H_*S_;
    float* X = (gw < NW) ? Xq : Xk;
    int w = (gw < NW) ? gw : gw - NW;
    if (w >= NW) return;
    int s = w & (S_ - 1);

    float2 v = *(float2*)&X[(size_t)w * D_ + lane * 2];
    float c  = cosT[s * 32 + lane];
    float sn = sinT[s * 32 + lane];
    float r0 = v.x * c - v.y * sn;
    float r1 = v.x * sn + v.y * c;

    float ss = r0 * r0 + r1 * r1;
    #pragma unroll
    for (int o = 16; o; o >>= 1) ss += __shfl_xor_sync(0xffffffffu, ss, o);
    float n   = sqrtf(ss);
    float inv = 1.0f / fmaxf(n, 1e-12f);

    *(float2*)&X[(size_t)w * D_ + lane * 2] = make_float2(r0 * inv, r1 * inv);
}

// ----------------------------------------------------------------------------
// Flash-style attention with tf32 tensor cores.
// One block per (b,h,q-tile of 64 rows); 8 warps; warp tile = 16(q) x 32.
//   QK^T: single tf32 (q,k are unit vectors -> score abs err ~6e-5; safe).
//         temperature folded into Q at staging: (temp*q).k == temp*(q.k).
//   PV:   tf32x3. V staged ROW-MAJOR (VsH/VsL [kc][d], stride 68): staging is
//         coalesced uint4 STS, conflict-free; PV B-fragments read
//         Vs[(ks+ct)*68 + d] / +4*68 (col-major k=kc, n=d semantics
//         preserved), bank pattern (4ct+g) mod 32 -> at most 2-way.
// Q/K fragment LDS pattern (4g+ct) -> conflict-free.
// Online softmax fp32 (quartet-parallel); PV accumulators persist in
// registers with flash rescale before each tile's mma batch.
// Dynamic smem: (5*64*68 + 192)*4 = 87808 B -> 2 CTAs/SM.
// ----------------------------------------------------------------------------
#define AST_ 68

extern __shared__ unsigned sm_u[];

__global__ __launch_bounds__(256, 2) void attention_kernel(
    const float* __restrict__ Qg, const float* __restrict__ Kg,
    const float* __restrict__ Vg, const float* __restrict__ tempPtr,
    float* __restrict__ ctx)
{
    unsigned* Qs  = sm_u;                   // [64][AST_] tf32 bits
    unsigned* Ks  = sm_u + 64*AST_;
    unsigned* VsH = sm_u + 2*64*AST_;       // row-major V, hi part [kc][d]
    unsigned* VsL = sm_u + 3*64*AST_;       // row-major V, lo part
    float*    Ss  = (float*)(sm_u + 4*64*AST_);   // scores/probs (fp32)
    float*    m_s  = (float*)(sm_u + 5*64*AST_);
    float*    l_s  = m_s + 64;
    float*    sc_s = l_s + 64;

    int t    = threadIdx.x;
    int w    = t >> 5, lane = t & 31;
    int g    = lane >> 2, ct = lane & 3;
    int mb   = (w & 3) * 16;               // warp's q-row base
    int nb   = (w >> 2) * 32;              // warp's col base (kc / d)

    int bh = blockIdx.x >> 3;
    int qt = blockIdx.x & 7;
    int b  = bh >> 4, h = bh & 15;

    const float temp = *tempPtr;
    const float* Q = Qg + (size_t)bh * S_ * D_ + (size_t)qt * 64 * D_;
    const float* K = Kg + (size_t)bh * S_ * D_;
    const float* V = Vg + (size_t)bh * S_ * D_;

    // Staging coordinates: 1024 float4 chunks over 256 threads
    int lrr[4], lds_[4];
    #pragma unroll
    for (int u = 0; u < 4; u++) {
        int i = t + u * 256;
        lrr[u]  = i >> 4;            // row 0..63
        lds_[u] = (i & 15) * 4;      // d-offset 0..60
    }

    // Stage Q (row-major, single tf32) with temperature folded in
    #pragma unroll
    for (int u = 0; u < 4; u++) {
        float4 qv = *(const float4*)&Q[lrr[u] * 64 + lds_[u]];
        uint4 p = {f2tf32(qv.x * temp), f2tf32(qv.y * temp),
                   f2tf32(qv.z * temp), f2tf32(qv.w * temp)};
        *(uint4*)&Qs[lrr[u] * AST_ + lds_[u]] = p;
    }
    if (t < 64) { m_s[t] = -1e30f; l_s[t] = 0.f; }

    // Prefetch K/V tile 0
    float4 kpre[4], vpre[4];
    #pragma unroll
    for (int u = 0; u < 4; u++) {
        kpre[u] = *(const float4*)&K[lrr[u] * 64 + lds_[u]];
        vpre[u] = *(const float4*)&V[lrr[u] * 64 + lds_[u]];
    }

    float acc[4][4];   // PV accumulator: 4 n-tiles x {c0..c3}
    #pragma unroll
    for (int i = 0; i < 4; i++)
        #pragma unroll
        for (int j = 0; j < 4; j++) acc[i][j] = 0.f;

    int sr = t >> 2;            // softmax row
    int sq = (t & 3) * 16;      // softmax column segment

    for (int kt = 0; kt < 8; kt++) {
        __syncthreads();   // all reads of Ks/Vs/Ss from previous iter done
        // Stage K + V row-major (tf32 / hi-lo split), all coalesced uint4.
        // K-store and V-split interleave per chunk: kpre[u]/vpre[u] are
        // consumed immediately, shortening register liveness.
        #pragma unroll
        for (int u = 0; u < 4; u++) {
            int r = lrr[u], ds = lds_[u];
            uint4 pk = {f2tf32(kpre[u].x), f2tf32(kpre[u].y),
                        f2tf32(kpre[u].z), f2tf32(kpre[u].w)};
            *(uint4*)&Ks[r * AST_ + ds] = pk;
            uint4 vh, vl;
            split_tf32(vpre[u].x, vh.x, vl.x);
            split_tf32(vpre[u].y, vh.y, vl.y);
            split_tf32(vpre[u].z, vh.z, vl.z);
            split_tf32(vpre[u].w, vh.w, vl.w);
            *(uint4*)&VsH[r * AST_ + ds] = vh;
            *(uint4*)&VsL[r * AST_ + ds] = vl;
        }
        __syncthreads();

        // Prefetch tile kt+1 (overlaps with compute below)
        if (kt < 7) {
            const float* Kn = K + (kt + 1) * 64 * 64;
            const float* Vn = V + (kt + 1) * 64 * 64;
            #pragma unroll
            for (int u = 0; u < 4; u++) {
                kpre[u] = *(const float4*)&Kn[lrr[u] * 64 + lds_[u]];
                vpre[u] = *(const float4*)&Vn[lrr[u] * 64 + lds_[u]];
            }
        }

        // QK^T: warp computes 16x32 of the 64x64 score tile (single tf32)
        float sacc[4][4];
        #pragma unroll
        for (int i = 0; i < 4; i++)
            #pragma unroll
            for (int j = 0; j < 4; j++) sacc[i][j] = 0.f;

        #pragma unroll
        for (int ks = 0; ks < 64; ks += 8) {
            unsigned af[4], bf[4][2];
            int abase = (mb + g) * AST_ + ks + ct;
            af[0] = Qs[abase];
            af[1] = Qs[abase + 8 * AST_];
            af[2] = Qs[abase + 4];
            af[3] = Qs[abase + 8 * AST_ + 4];
            #pragma unroll
            for (int nt = 0; nt < 4; nt++) {
                int bbase = (nb + nt * 8 + g) * AST_ + ks + ct;
                bf[nt][0] = Ks[bbase];
                bf[nt][1] = Ks[bbase + 4];
            }
            #pragma unroll
            for (int nt = 0; nt < 4; nt++)
                mma_tf32(sacc[nt], af, bf[nt]);
        }
        // scores -> Ss (temp already folded into Q)
        #pragma unroll
        for (int nt = 0; nt < 4; nt++) {
            int col = nb + nt * 8 + ct * 2;
            *(float2*)&Ss[(mb + g) * AST_ + col] =
                make_float2(sacc[nt][0], sacc[nt][1]);
            *(float2*)&Ss[(mb + g + 8) * AST_ + col] =
                make_float2(sacc[nt][2], sacc[nt][3]);
        }
        __syncthreads();

        // Online softmax: 4 threads per row, quartet reduction via shfl
        {
            float mold = m_s[sr];
            float mx = -1e30f;
            #pragma unroll
            for (int c = 0; c < 16; c++)
                mx = fmaxf(mx, Ss[sr * AST_ + sq + c]);
            mx = fmaxf(mx, __shfl_xor_sync(0xffffffffu, mx, 1));
            mx = fmaxf(mx, __shfl_xor_sync(0xffffffffu, mx, 2));
            mx = fmaxf(mx, mold);

            float sum = 0.f;
            #pragma unroll
            for (int c = 0; c < 16; c++) {
                float p = __expf(Ss[sr * AST_ + sq + c] - mx);
                Ss[sr * AST_ + sq + c] = p;
                sum += p;
            }
            sum += __shfl_xor_sync(0xffffffffu, sum, 1);
            sum += __shfl_xor_sync(0xffffffffu, sum, 2);

            if ((t & 3) == 0) {
                float corr = __expf(mold - mx);
                m_s[sr]  = mx;
                l_s[sr]  = l_s[sr] * corr + sum;
                sc_s[sr] = corr;
            }
        }
        __syncthreads();

        // PV (tf32x3): rescale persistent acc, then acc += P(16x64).V(64x32)
        // B-fragment (col-major k=kc, n=d): b0 = Vs[ks+ct][d], b1 = Vs[ks+ct+4][d]
        {
            float corr0 = sc_s[mb + g];
            float corr1 = sc_s[mb + g + 8];
            #pragma unroll
            for (int nt = 0; nt < 4; nt++) {
                acc[nt][0] *= corr0; acc[nt][1] *= corr0;
                acc[nt][2] *= corr1; acc[nt][3] *= corr1;
            }
            #pragma unroll
            for (int ks = 0; ks < 64; ks += 8) {
                int abase = (mb + g) * AST_ + ks + ct;
                float p0 = Ss[abase];
                float p1 = Ss[abase + 8 * AST_];
                float p2 = Ss[abase + 4];
                float p3 = Ss[abase + 8 * AST_ + 4];
                unsigned afh[4], afl[4];
                split_tf32(p0, afh[0], afl[0]);
                split_tf32(p1, afh[1], afl[1]);
                split_tf32(p2, afh[2], afl[2]);
                split_tf32(p3, afh[3], afl[3]);
                int brow = (ks + ct) * AST_;
                #pragma unroll
                for (int nt = 0; nt < 4; nt++) {
                    int bcol = nb + nt * 8 + g;
                    unsigned bfh[2] = {VsH[brow + bcol],
                                       VsH[brow + 4 * AST_ + bcol]};
                    unsigned bfl[2] = {VsL[brow + bcol],
                                       VsL[brow + 4 * AST_ + bcol]};
                    mma_tf32(acc[nt], afh, bfh);
                    mma_tf32(acc[nt], afh, bfl);
                    mma_tf32(acc[nt], afl, bfh);
                }
            }
        }
    }

    // Normalize and store into ctx [B,S,E]
    {
        int r0 = mb + g, r1 = mb + g + 8;
        float inv0 = 1.0f / l_s[r0];
        float inv1 = 1.0f / l_s[r1];
        int s0 = qt * 64 + r0, s1 = qt * 64 + r1;
        #pragma unroll
        for (int nt = 0; nt < 4; nt++) {
            int col = h * 64 + nb + nt * 8 + ct * 2;
            *(float2*)&ctx[((size_t)(b * S_ + s0)) * E_ + col] =
                make_float2(acc[nt][0] * inv0, acc[nt][1] * inv0);
            *(float2*)&ctx[((size_t)(b * S_ + s1)) * E_ + col] =
                make_float2(acc[nt][2] * inv1, acc[nt][3] * inv1);
        }
    }
}

// ----------------------------------------------------------------------------
// Launch
// ----------------------------------------------------------------------------
extern "C" void kernel_launch(void* const* d_in, const int* in_sizes, int n_in,
                              void* d_out, int out_size)
{
    const float* x_q  = (const float*)d_in[0];
    const float* x_k  = (const float*)d_in[1];
    const float* x_v  = (const float*)d_in[2];
    const float* Wq   = (const float*)d_in[3];
    const float* bq   = (const float*)d_in[4];
    const float* Wk   = (const float*)d_in[5];
    const float* bk   = (const float*)d_in[6];
    const float* Wv   = (const float*)d_in[7];
    const float* bv   = (const float*)d_in[8];
    const float* Wo   = (const float*)d_in[9];
    const float* bo   = (const float*)d_in[10];
    const float* temp = (const float*)d_in[11];
    const float* cosT = (const float*)d_in[12];
    const float* sinT = (const float*)d_in[13];
    float* out = (float*)d_out;

    float *q, *k, *v, *ctx;
    cudaGetSymbolAddress((void**)&q,   g_q);
    cudaGetSymbolAddress((void**)&k,   g_k);
    cudaGetSymbolAddress((void**)&v,   g_v);
    cudaGetSymbolAddress((void**)&ctx, g_ctx);

    // Opt-in to >48KB dynamic smem (attribute set; not a stream op, capture-safe)
    cudaFuncSetAttribute(qkv_proj_kernel,
                         cudaFuncAttributeMaxDynamicSharedMemorySize, GSMEM_BYTES_);
    cudaFuncSetAttribute(out_proj_kernel,
                         cudaFuncAttributeMaxDynamicSharedMemorySize, GSMEM_BYTES_);

    dim3 qkvGrid(E_/128, M_/128, 3);   // (8, 32, 3) = 768 CTAs
    qkv_proj_kernel<<<qkvGrid, 256, GSMEM_BYTES_>>>(x_q, x_k, x_v, Wq, Wk, Wv,
                                                    bq, bk, bv, q, k, v);

    int ropeBlocks = (2 * B_*H_*S_ * 32) / 256;   // 16384 (q and k fused)
    rope_l2norm_kernel<<<ropeBlocks, 256>>>(q, k, cosT, sinT);

    const int attnSmem = (5*64*AST_ + 192) * 4;   // 87808 B
    cudaFuncSetAttribute(attention_kernel,
                         cudaFuncAttributeMaxDynamicSharedMemorySize, attnSmem);
    attention_kernel<<<B_*H_*QT_, 256, attnSmem>>>(q, k, v, temp, ctx);

    dim3 oGrid(E_/128, M_/128);   // (8, 32)
    out_proj_kernel<<<oGrid, 256, GSMEM_BYTES_>>>(ctx, Wo, bo, out);
}

// round 15
// speedup vs baseline: 1.5276x; 1.5276x over previous
#include <cuda_runtime.h>
#include <cuda_bf16.h>

// Problem constants
#define B_ 8
#define S_ 512
#define E_ 1024
#define H_ 16
#define D_ 64
#define M_ (B_*S_)     // 4096 rows for projection GEMMs
#define QT_ (S_/64)    // 8 q-tiles per (b,h)

// Scratch: __device__ globals (no allocation allowed anywhere)
__device__ float g_q[B_*H_*S_*D_];    // 16 MB, [B,H,S,D]
__device__ float g_k[B_*H_*S_*D_];
__device__ float g_v[B_*H_*S_*D_];
__device__ float g_ctx[B_*S_*E_];     // 16 MB, [B,S,E]

// ----------------------------------------------------------------------------
// tf32 helpers (PTX-ISA m16n8k8 fragment conventions, sm_80 lineage):
//   A row-major:  a0=(g,ct) a1=(g+8,ct) a2=(g,ct+4) a3=(g+8,ct+4)
//   B col-major:  b0=(k=ct,n=g) b1=(k=ct+4,n=g)
//   C:            c0/c1=(g,2ct/2ct+1) c2/c3=(g+8,.)
// with g=lane>>2, ct=lane&3.
// Precision plan (validated by measured rel_err=4.06e-5 on the all-x3 build):
//   - All four projections: single tf32 (rna), ~2.4e-4 per GEMM.
//   - QK^T: single tf32 on unit vectors (~5e-5 at scores).
//   - PV: tf32x3 anchor (error ~2^-22).
//   Total predicted rel_err ~3.5e-4 < 1e-3 with 2.8x margin.
// ----------------------------------------------------------------------------
__device__ __forceinline__ unsigned f2tf32(float x) {
    unsigned r;
    asm("cvt.rna.tf32.f32 %0, %1;" : "=r"(r) : "f"(x));
    return r;
}
__device__ __forceinline__ void split_tf32(float x, unsigned& hi, unsigned& lo) {
    hi = f2tf32(x);
    lo = f2tf32(x - __uint_as_float(hi));
}

__device__ __forceinline__ void mma_tf32(float* d, const unsigned* a,
                                         const unsigned* b) {
    asm("mma.sync.aligned.m16n8k8.row.col.f32.tf32.tf32.f32 "
        "{%0,%1,%2,%3}, {%4,%5,%6,%7}, {%8,%9}, {%0,%1,%2,%3};\n"
        : "+f"(d[0]), "+f"(d[1]), "+f"(d[2]), "+f"(d[3])
        : "r"(a[0]), "r"(a[1]), "r"(a[2]), "r"(a[3]),
          "r"(b[0]), "r"(b[1]));
}

#define GST_ 20
#define KT_ 16
#define GPLANE_ (128 * GST_)               // 2560 words per plane
#define QSMEM_BYTES_ (4 * GPLANE_ * 4)     // 2 bufs x 2 planes = 40960 B

extern __shared__ unsigned gsm[];

// ----------------------------------------------------------------------------
// Single-tf32 GEMM body: C[m,n] = sum_k A[m,k]*W[n,k] + bias[n].
// Used for ALL four projections (measured headroom funds ~2.4e-4/GEMM).
// CTA tile 128x128, K-tile 16, double-buffered smem (40KB dynamic) +
// register prefetch; ONE barrier per k-tile. 8 warps (2x4); warp tile
// 64x32 = 4x4 m16n8k8 per k-step of 8. Smem row stride 20 words ->
// fragment LDS (g*20+ct) hits 32 distinct banks, conflict-free.
// head_layout=1 remaps store (m,n) -> [B,H,S,D].
// ----------------------------------------------------------------------------
__device__ __forceinline__ void gemm_tf32x1_body(
    const float* __restrict__ A, const float* __restrict__ W,
    const float* __restrict__ bias, float* __restrict__ C,
    int row0, int col0, int head_layout)
{
    unsigned* As = gsm;                  // 2 bufs x 2560
    unsigned* Ws = gsm + 2 * GPLANE_;

    int t    = threadIdx.x;
    int w    = t >> 5, lane = t & 31;
    int g    = lane >> 2, ct = lane & 3;
    int wm   = w & 1,  wn = w >> 1;
    int mbase = wm * 64, nbase = wn * 32;

    int lr = t >> 1;
    int lk = (t & 1) * 8;

    const float* Ap = A + (size_t)(row0 + lr) * E_ + lk;
    const float* Wp = W + (size_t)(col0 + lr) * E_ + lk;

    float2 bias_pre[4];
    #pragma unroll
    for (int nt = 0; nt < 4; nt++)
        bias_pre[nt] = *(const float2*)&bias[col0 + nbase + nt * 8 + ct * 2];

    float acc[4][4][4];
    #pragma unroll
    for (int i = 0; i < 4; i++)
        #pragma unroll
        for (int j = 0; j < 4; j++)
            #pragma unroll
            for (int r = 0; r < 4; r++) acc[i][j][r] = 0.f;

    {
        float av[8], wv[8];
        *(float4*)&av[0] = *(const float4*)(Ap);
        *(float4*)&av[4] = *(const float4*)(Ap + 4);
        *(float4*)&wv[0] = *(const float4*)(Wp);
        *(float4*)&wv[4] = *(const float4*)(Wp + 4);
        #pragma unroll
        for (int i = 0; i < 8; i++) {
            As[lr * GST_ + lk + i] = f2tf32(av[i]);
            Ws[lr * GST_ + lk + i] = f2tf32(wv[i]);
        }
    }
    __syncthreads();

    int buf = 0;
    for (int k0 = KT_; k0 <= E_; k0 += KT_) {
        float av[8], wv[8];
        if (k0 < E_) {
            *(float4*)&av[0] = *(const float4*)(Ap + k0);
            *(float4*)&av[4] = *(const float4*)(Ap + k0 + 4);
            *(float4*)&wv[0] = *(const float4*)(Wp + k0);
            *(float4*)&wv[4] = *(const float4*)(Wp + k0 + 4);
        }

        int bo = buf * GPLANE_;
        #pragma unroll
        for (int ks = 0; ks < KT_; ks += 8) {
            unsigned bf[4][2];
            #pragma unroll
            for (int nt = 0; nt < 4; nt++) {
                int base = bo + (nbase + nt * 8 + g) * GST_ + ks + ct;
                bf[nt][0] = Ws[base]; bf[nt][1] = Ws[base + 4];
            }
            #pragma unroll
            for (int mt = 0; mt < 4; mt++) {
                int base = bo + (mbase + mt * 16 + g) * GST_ + ks + ct;
                unsigned af[4] = {As[base], As[base + 8 * GST_],
                                  As[base + 4], As[base + 8 * GST_ + 4]};
                #pragma unroll
                for (int nt = 0; nt < 4; nt++)
                    mma_tf32(acc[mt][nt], af, bf[nt]);
            }
        }

        if (k0 < E_) {
            int nbuf = buf ^ 1;
            int no = nbuf * GPLANE_;
            #pragma unroll
            for (int i = 0; i < 8; i++) {
                As[no + lr * GST_ + lk + i] = f2tf32(av[i]);
                Ws[no + lr * GST_ + lk + i] = f2tf32(wv[i]);
            }
            __syncthreads();
            buf = nbuf;
        }
    }

    // Epilogue: bias (prefetched) + store
    #pragma unroll
    for (int mt = 0; mt < 4; mt++) {
        int r = row0 + mbase + mt * 16 + g;
        #pragma unroll
        for (int nt = 0; nt < 4; nt++) {
            int c = col0 + nbase + nt * 8 + ct * 2;
            float2 bv = bias_pre[nt];
            float2 lo = make_float2(acc[mt][nt][0] + bv.x,
                                    acc[mt][nt][1] + bv.y);
            float2 hi = make_float2(acc[mt][nt][2] + bv.x,
                                    acc[mt][nt][3] + bv.y);
            if (head_layout) {
                int hh = c >> 6, dd = c & 63;
                int bb0 = r >> 9, ss0 = r & 511;
                int r2 = r + 8;
                int bb1 = r2 >> 9, ss1 = r2 & 511;
                *(float2*)&C[(((size_t)(bb0*H_ + hh))*S_ + ss0)*D_ + dd] = lo;
                *(float2*)&C[(((size_t)(bb1*H_ + hh))*S_ + ss1)*D_ + dd] = hi;
            } else {
                *(float2*)&C[(size_t)r * E_ + c]       = lo;
                *(float2*)&C[(size_t)(r + 8) * E_ + c] = hi;
            }
        }
    }
}

// Fused Q/K/V projections: gridDim.z = 3 selects operands.
__global__ __launch_bounds__(256, 2) void qkv_proj_kernel(
    const float* __restrict__ xq, const float* __restrict__ xk,
    const float* __restrict__ xv,
    const float* __restrict__ Wq, const float* __restrict__ Wk,
    const float* __restrict__ Wv,
    const float* __restrict__ bq, const float* __restrict__ bk,
    const float* __restrict__ bv,
    float* __restrict__ q, float* __restrict__ k, float* __restrict__ v)
{
    int z = blockIdx.z;
    const float* A    = (z == 0) ? xq : (z == 1) ? xk : xv;
    const float* W    = (z == 0) ? Wq : (z == 1) ? Wk : Wv;
    const float* bias = (z == 0) ? bq : (z == 1) ? bk : bv;
    float*       C    = (z == 0) ? q  : (z == 1) ? k  : v;
    gemm_tf32x1_body(A, W, bias, C, blockIdx.y * 128, blockIdx.x * 128, 1);
}

// Output projection (single tf32, flat store)
__global__ __launch_bounds__(256, 2) void out_proj_kernel(
    const float* __restrict__ A, const float* __restrict__ W,
    const float* __restrict__ bias, float* __restrict__ C)
{
    gemm_tf32x1_body(A, W, bias, C, blockIdx.y * 128, blockIdx.x * 128, 0);
}

// ----------------------------------------------------------------------------
// Fused RoPE (interleaved pairs) + L2 normalization, in-place on [B,H,S,D].
// One warp per (b,h,s) row; lane owns pair (2*lane, 2*lane+1).
// Processes BOTH q and k in one launch (second half of grid -> k).
// ----------------------------------------------------------------------------
__global__ __launch_bounds__(256) void rope_l2norm_kernel(
    float* __restrict__ Xq, float* __restrict__ Xk,
    const float* __restrict__ cosT, const float* __restrict__ sinT)
{
    int gw   = (blockIdx.x * blockDim.x + threadIdx.x) >> 5;
    int lane = threadIdx.x & 31;
    const int NW = B_*H_*S_;
    float* X = (gw < NW) ? Xq : Xk;
    int w = (gw < NW) ? gw : gw - NW;
    if (w >= NW) return;
    int s = w & (S_ - 1);

    float2 v = *(float2*)&X[(size_t)w * D_ + lane * 2];
    float c  = cosT[s * 32 + lane];
    float sn = sinT[s * 32 + lane];
    float r0 = v.x * c - v.y * sn;
    float r1 = v.x * sn + v.y * c;

    float ss = r0 * r0 + r1 * r1;
    #pragma unroll
    for (int o = 16; o; o >>= 1) ss += __shfl_xor_sync(0xffffffffu, ss, o);
    float n   = sqrtf(ss);
    float inv = 1.0f / fmaxf(n, 1e-12f);

    *(float2*)&X[(size_t)w * D_ + lane * 2] = make_float2(r0 * inv, r1 * inv);
}

// ----------------------------------------------------------------------------
// Flash-style attention with tf32 tensor cores (unchanged from measured R13).
// QK^T single tf32 (temp folded into Q); PV tf32x3 with row-major V planes.
// Dynamic smem: (5*64*68 + 192)*4 = 87808 B -> 2 CTAs/SM.
// ----------------------------------------------------------------------------
#define AST_ 68

extern __shared__ unsigned sm_u[];

__global__ __launch_bounds__(256, 2) void attention_kernel(
    const float* __restrict__ Qg, const float* __restrict__ Kg,
    const float* __restrict__ Vg, const float* __restrict__ tempPtr,
    float* __restrict__ ctx)
{
    unsigned* Qs  = sm_u;                   // [64][AST_] tf32 bits
    unsigned* Ks  = sm_u + 64*AST_;
    unsigned* VsH = sm_u + 2*64*AST_;       // row-major V, hi part [kc][d]
    unsigned* VsL = sm_u + 3*64*AST_;       // row-major V, lo part
    float*    Ss  = (float*)(sm_u + 4*64*AST_);   // scores/probs (fp32)
    float*    m_s  = (float*)(sm_u + 5*64*AST_);
    float*    l_s  = m_s + 64;
    float*    sc_s = l_s + 64;

    int t    = threadIdx.x;
    int w    = t >> 5, lane = t & 31;
    int g    = lane >> 2, ct = lane & 3;
    int mb   = (w & 3) * 16;               // warp's q-row base
    int nb   = (w >> 2) * 32;              // warp's col base (kc / d)

    int bh = blockIdx.x >> 3;
    int qt = blockIdx.x & 7;
    int b  = bh >> 4, h = bh & 15;

    const float temp = *tempPtr;
    const float* Q = Qg + (size_t)bh * S_ * D_ + (size_t)qt * 64 * D_;
    const float* K = Kg + (size_t)bh * S_ * D_;
    const float* V = Vg + (size_t)bh * S_ * D_;

    int lrr[4], lds_[4];
    #pragma unroll
    for (int u = 0; u < 4; u++) {
        int i = t + u * 256;
        lrr[u]  = i >> 4;            // row 0..63
        lds_[u] = (i & 15) * 4;      // d-offset 0..60
    }

    // Stage Q (single tf32) with temperature folded in
    #pragma unroll
    for (int u = 0; u < 4; u++) {
        float4 qv = *(const float4*)&Q[lrr[u] * 64 + lds_[u]];
        uint4 p = {f2tf32(qv.x * temp), f2tf32(qv.y * temp),
                   f2tf32(qv.z * temp), f2tf32(qv.w * temp)};
        *(uint4*)&Qs[lrr[u] * AST_ + lds_[u]] = p;
    }
    if (t < 64) { m_s[t] = -1e30f; l_s[t] = 0.f; }

    float4 kpre[4], vpre[4];
    #pragma unroll
    for (int u = 0; u < 4; u++) {
        kpre[u] = *(const float4*)&K[lrr[u] * 64 + lds_[u]];
        vpre[u] = *(const float4*)&V[lrr[u] * 64 + lds_[u]];
    }

    float acc[4][4];
    #pragma unroll
    for (int i = 0; i < 4; i++)
        #pragma unroll
        for (int j = 0; j < 4; j++) acc[i][j] = 0.f;

    int sr = t >> 2;
    int sq = (t & 3) * 16;

    for (int kt = 0; kt < 8; kt++) {
        __syncthreads();
        #pragma unroll
        for (int u = 0; u < 4; u++) {
            int r = lrr[u], ds = lds_[u];
            uint4 pk = {f2tf32(kpre[u].x), f2tf32(kpre[u].y),
                        f2tf32(kpre[u].z), f2tf32(kpre[u].w)};
            *(uint4*)&Ks[r * AST_ + ds] = pk;
            uint4 vh, vl;
            split_tf32(vpre[u].x, vh.x, vl.x);
            split_tf32(vpre[u].y, vh.y, vl.y);
            split_tf32(vpre[u].z, vh.z, vl.z);
            split_tf32(vpre[u].w, vh.w, vl.w);
            *(uint4*)&VsH[r * AST_ + ds] = vh;
            *(uint4*)&VsL[r * AST_ + ds] = vl;
        }
        __syncthreads();

        if (kt < 7) {
            const float* Kn = K + (kt + 1) * 64 * 64;
            const float* Vn = V + (kt + 1) * 64 * 64;
            #pragma unroll
            for (int u = 0; u < 4; u++) {
                kpre[u] = *(const float4*)&Kn[lrr[u] * 64 + lds_[u]];
                vpre[u] = *(const float4*)&Vn[lrr[u] * 64 + lds_[u]];
            }
        }

        // QK^T
        float sacc[4][4];
        #pragma unroll
        for (int i = 0; i < 4; i++)
            #pragma unroll
            for (int j = 0; j < 4; j++) sacc[i][j] = 0.f;

        #pragma unroll
        for (int ks = 0; ks < 64; ks += 8) {
            unsigned af[4], bf[4][2];
            int abase = (mb + g) * AST_ + ks + ct;
            af[0] = Qs[abase];
            af[1] = Qs[abase + 8 * AST_];
            af[2] = Qs[abase + 4];
            af[3] = Qs[abase + 8 * AST_ + 4];
            #pragma unroll
            for (int nt = 0; nt < 4; nt++) {
                int bbase = (nb + nt * 8 + g) * AST_ + ks + ct;
                bf[nt][0] = Ks[bbase];
                bf[nt][1] = Ks[bbase + 4];
            }
            #pragma unroll
            for (int nt = 0; nt < 4; nt++)
                mma_tf32(sacc[nt], af, bf[nt]);
        }
        #pragma unroll
        for (int nt = 0; nt < 4; nt++) {
            int col = nb + nt * 8 + ct * 2;
            *(float2*)&Ss[(mb + g) * AST_ + col] =
                make_float2(sacc[nt][0], sacc[nt][1]);
            *(float2*)&Ss[(mb + g + 8) * AST_ + col] =
                make_float2(sacc[nt][2], sacc[nt][3]);
        }
        __syncthreads();

        // Online softmax: 4 threads/row + shfl quartet reduction
        {
            float mold = m_s[sr];
            float mx = -1e30f;
            #pragma unroll
            for (int c = 0; c < 16; c++)
                mx = fmaxf(mx, Ss[sr * AST_ + sq + c]);
            mx = fmaxf(mx, __shfl_xor_sync(0xffffffffu, mx, 1));
            mx = fmaxf(mx, __shfl_xor_sync(0xffffffffu, mx, 2));
            mx = fmaxf(mx, mold);

            float sum = 0.f;
            #pragma unroll
            for (int c = 0; c < 16; c++) {
                float p = __expf(Ss[sr * AST_ + sq + c] - mx);
                Ss[sr * AST_ + sq + c] = p;
                sum += p;
            }
            sum += __shfl_xor_sync(0xffffffffu, sum, 1);
            sum += __shfl_xor_sync(0xffffffffu, sum, 2);

            if ((t & 3) == 0) {
                float corr = __expf(mold - mx);
                m_s[sr]  = mx;
                l_s[sr]  = l_s[sr] * corr + sum;
                sc_s[sr] = corr;
            }
        }
        __syncthreads();

        // PV (tf32x3)
        {
            float corr0 = sc_s[mb + g];
            float corr1 = sc_s[mb + g + 8];
            #pragma unroll
            for (int nt = 0; nt < 4; nt++) {
                acc[nt][0] *= corr0; acc[nt][1] *= corr0;
                acc[nt][2] *= corr1; acc[nt][3] *= corr1;
            }
            #pragma unroll
            for (int ks = 0; ks < 64; ks += 8) {
                int abase = (mb + g) * AST_ + ks + ct;
                float p0 = Ss[abase];
                float p1 = Ss[abase + 8 * AST_];
                float p2 = Ss[abase + 4];
                float p3 = Ss[abase + 8 * AST_ + 4];
                unsigned afh[4], afl[4];
                split_tf32(p0, afh[0], afl[0]);
                split_tf32(p1, afh[1], afl[1]);
                split_tf32(p2, afh[2], afl[2]);
                split_tf32(p3, afh[3], afl[3]);
                int brow = (ks + ct) * AST_;
                #pragma unroll
                for (int nt = 0; nt < 4; nt++) {
                    int bcol = nb + nt * 8 + g;
                    unsigned bfh[2] = {VsH[brow + bcol],
                                       VsH[brow + 4 * AST_ + bcol]};
                    unsigned bfl[2] = {VsL[brow + bcol],
                                       VsL[brow + 4 * AST_ + bcol]};
                    mma_tf32(acc[nt], afh, bfh);
                    mma_tf32(acc[nt], afh, bfl);
                    mma_tf32(acc[nt], afl, bfh);
                }
            }
        }
    }

    // Normalize and store into ctx [B,S,E]
    {
        int r0 = mb + g, r1 = mb + g + 8;
        float inv0 = 1.0f / l_s[r0];
        float inv1 = 1.0f / l_s[r1];
        int s0 = qt * 64 + r0, s1 = qt * 64 + r1;
        #pragma unroll
        for (int nt = 0; nt < 4; nt++) {
            int col = h * 64 + nb + nt * 8 + ct * 2;
            *(float2*)&ctx[((size_t)(b * S_ + s0)) * E_ + col] =
                make_float2(acc[nt][0] * inv0, acc[nt][1] * inv0);
            *(float2*)&ctx[((size_t)(b * S_ + s1)) * E_ + col] =
                make_float2(acc[nt][2] * inv1, acc[nt][3] * inv1);
        }
    }
}

// ----------------------------------------------------------------------------
// Launch
// ----------------------------------------------------------------------------
extern "C" void kernel_launch(void* const* d_in, const int* in_sizes, int n_in,
                              void* d_out, int out_size)
{
    const float* x_q  = (const float*)d_in[0];
    const float* x_k  = (const float*)d_in[1];
    const float* x_v  = (const float*)d_in[2];
    const float* Wq   = (const float*)d_in[3];
    const float* bq   = (const float*)d_in[4];
    const float* Wk   = (const float*)d_in[5];
    const float* bk   = (const float*)d_in[6];
    const float* Wv   = (const float*)d_in[7];
    const float* bv   = (const float*)d_in[8];
    const float* Wo   = (const float*)d_in[9];
    const float* bo   = (const float*)d_in[10];
    const float* temp = (const float*)d_in[11];
    const float* cosT = (const float*)d_in[12];
    const float* sinT = (const float*)d_in[13];
    float* out = (float*)d_out;

    float *q, *k, *v, *ctx;
    cudaGetSymbolAddress((void**)&q,   g_q);
    cudaGetSymbolAddress((void**)&k,   g_k);
    cudaGetSymbolAddress((void**)&v,   g_v);
    cudaGetSymbolAddress((void**)&ctx, g_ctx);

    cudaFuncSetAttribute(qkv_proj_kernel,
                         cudaFuncAttributeMaxDynamicSharedMemorySize, QSMEM_BYTES_);
    cudaFuncSetAttribute(out_proj_kernel,
                         cudaFuncAttributeMaxDynamicSharedMemorySize, QSMEM_BYTES_);

    dim3 qkvGrid(E_/128, M_/128, 3);   // (8, 32, 3) = 768 CTAs
    qkv_proj_kernel<<<qkvGrid, 256, QSMEM_BYTES_>>>(x_q, x_k, x_v, Wq, Wk, Wv,
                                                    bq, bk, bv, q, k, v);

    int ropeBlocks = (2 * B_*H_*S_ * 32) / 256;   // 16384 (q and k fused)
    rope_l2norm_kernel<<<ropeBlocks, 256>>>(q, k, cosT, sinT);

    const int attnSmem = (5*64*AST_ + 192) * 4;   // 87808 B
    cudaFuncSetAttribute(attention_kernel,
                         cudaFuncAttributeMaxDynamicSharedMemorySize, attnSmem);
    attention_kernel<<<B_*H_*QT_, 256, attnSmem>>>(q, k, v, temp, ctx);

    dim3 oGrid(E_/128, M_/128);   // (8, 32)
    out_proj_kernel<<<oGrid, 256, QSMEM_BYTES_>>>(ctx, Wo, bo, out);
}